// round 7
// baseline (speedup 1.0000x reference)
#include <cuda_runtime.h>
#include <cuda_bf16.h>
#include <cstdint>

#define BATCH 8192
#define NREF  2048
#define KDIM  256
#define MT    128             // M rows per CTA (4 warps x 32 rows)
#define NQ    512             // refs per CTA (grid = 64 mtiles x 4 quarters)
#define NT    64              // refs per tile
#define NTILES (NQ / NT)      // 8
#define ROWB  256             // bytes per fp8 row (256 e4m3)
#define LDB   272             // padded smem row stride (bytes)

__device__ unsigned char g_R8[NREF * KDIM];   // e4m3 bytes of (1-2R): +1->0x38, -1->0xB8
__device__ float         g_cntR[NREF];

struct Smem {
    char  B[2][NT * LDB];     // 2 x 17408 B
    float cntR[NQ];           // 2048 B
};
#define SMEM_SZ (int)sizeof(Smem)

// ---------------------------------------------------------------------------
__device__ __forceinline__ uint32_t s2u(const void* p) {
    uint32_t a;
    asm("{ .reg .u64 t; cvta.to.shared.u64 t, %1; cvt.u32.u64 %0, t; }" : "=r"(a) : "l"(p));
    return a;
}
__device__ __forceinline__ void cpa16(uint32_t dst, const void* src) {
    asm volatile("cp.async.cg.shared.global [%0], [%1], 16;" :: "r"(dst), "l"(src));
}
template <int N>
__device__ __forceinline__ void cpwait() {
    asm volatile("cp.async.wait_group %0;" :: "n"(N) : "memory");
}
// fp8 e4m3 MMA, f32 accum: 16x8x32
__device__ __forceinline__ void mma_fp8(float* c, const uint32_t* a, uint32_t b0, uint32_t b1) {
    asm volatile(
        "mma.sync.aligned.m16n8k32.row.col.f32.e4m3.e4m3.f32 "
        "{%0,%1,%2,%3},{%4,%5,%6,%7},{%8,%9},{%0,%1,%2,%3};"
        : "+f"(c[0]), "+f"(c[1]), "+f"(c[2]), "+f"(c[3])
        : "r"(a[0]), "r"(a[1]), "r"(a[2]), "r"(a[3]), "r"(b0), "r"(b1));
}
// pack 4 floats (each exactly 0.0 or 1.0) into 4 e4m3 bytes (0x00 / 0x38)
__device__ __forceinline__ uint32_t packA(float4 v) {
    uint32_t b0 = (uint32_t)v.x * 0x38u;
    uint32_t b1 = (uint32_t)v.y * 0x38u;
    uint32_t b2 = (uint32_t)v.z * 0x38u;
    uint32_t b3 = (uint32_t)v.w * 0x38u;
    return b0 | (b1 << 8) | (b2 << 16) | (b3 << 24);
}

// ---------------------------------------------------------------------------
// Kernel 1 (prep): out init, R fp32 -> e4m3 of (1-2R), cntR reduce. Exact.
// ---------------------------------------------------------------------------
__global__ void prep_kernel(const float* __restrict__ R, int* __restrict__ outi) {
    const int Rn4 = NREF * KDIM / 4;    // 131072
    int i = blockIdx.x * 256 + threadIdx.x;

    if (i < BATCH) outi[i] = 0x7f800000;   // +inf bits

    if (i < Rn4) {
        float4 v = reinterpret_cast<const float4*>(R)[i];
        // R==1 -> -1 (0xB8), R==0 -> +1 (0x38)
        uint32_t b0 = 0x38u | ((uint32_t)v.x << 7);
        uint32_t b1 = 0x38u | ((uint32_t)v.y << 7);
        uint32_t b2 = 0x38u | ((uint32_t)v.z << 7);
        uint32_t b3 = 0x38u | ((uint32_t)v.w << 7);
        reinterpret_cast<uint32_t*>(g_R8)[i] = b0 | (b1 << 8) | (b2 << 16) | (b3 << 24);
    } else if (i < Rn4 + NREF * 32) {
        int t = i - Rn4;
        int w = t >> 5, lane = t & 31;
        float s = 0.f;
        #pragma unroll
        for (int k = lane; k < KDIM; k += 32) s += R[w * KDIM + k];
        #pragma unroll
        for (int o = 16; o; o >>= 1) s += __shfl_xor_sync(0xffffffffu, s, o);
        if (lane == 0) g_cntR[w] = s;
    }
}

// ---------------------------------------------------------------------------
// Kernel 2 (main): fp8 e4m3 QMMA GEMM (k32 -> 2x MACs/instr vs bf16 k16).
// Warp owns 32 M-rows (2 A-tiles, B fragment reuse), A fragments packed
// from float input into registers, B double-buffered cp.async, fused min.
// ---------------------------------------------------------------------------
__device__ __forceinline__ void load_B(Smem& sm, int t, int buf, int quarter, int tid) {
    const char* src = (const char*)g_R8 + ((size_t)(quarter * NQ + t * NT)) * ROWB;
    #pragma unroll
    for (int j = 0; j < 8; j++) {            // 1024 x 16B chunks / 128 threads
        int i = tid + j * 128;
        int r = i >> 4, c = i & 15;          // 16 chunks per 256B row
        cpa16(s2u(&sm.B[buf][r * LDB + c * 16]), src + (size_t)r * ROWB + c * 16);
    }
    asm volatile("cp.async.commit_group;" ::: "memory");
}

__global__ void __launch_bounds__(128, 2) hamming_qmma(const float* __restrict__ S,
                                                       int* __restrict__ outi) {
    extern __shared__ __align__(16) char smraw[];
    Smem& sm = *reinterpret_cast<Smem*>(smraw);

    const int tid  = threadIdx.x;
    const int wid  = tid >> 5;
    const int lane = tid & 31;
    const int g    = lane >> 2;
    const int q    = lane & 3;
    const int mtile   = blockIdx.x >> 2;
    const int quarter = blockIdx.x & 3;

    load_B(sm, 0, 0, quarter, tid);                       // tile 0 in flight

    // A fragments: 2 m16-tiles x 8 k-steps (k32 each) x 4 regs = 64 regs
    uint32_t a[2][8][4];
    #pragma unroll
    for (int mt = 0; mt < 2; mt++) {
        const float* rowLo = S + ((size_t)(mtile * MT + wid * 32 + mt * 16 + g)) * KDIM;
        const float* rowHi = rowLo + 8 * KDIM;
        #pragma unroll
        for (int ks = 0; ks < 8; ks++) {
            int kb = ks * 32 + q * 4;
            a[mt][ks][0] = packA(*reinterpret_cast<const float4*>(rowLo + kb));
            a[mt][ks][1] = packA(*reinterpret_cast<const float4*>(rowHi + kb));
            a[mt][ks][2] = packA(*reinterpret_cast<const float4*>(rowLo + kb + 16));
            a[mt][ks][3] = packA(*reinterpret_cast<const float4*>(rowHi + kb + 16));
        }
    }
    for (int i = tid; i < NQ; i += 128) sm.cntR[i] = g_cntR[quarter * NQ + i];

    float rmin[2][2] = {{__int_as_float(0x7f800000), __int_as_float(0x7f800000)},
                        {__int_as_float(0x7f800000), __int_as_float(0x7f800000)}};

    for (int t = 0; t < NTILES; t++) {
        if (t + 1 < NTILES) {
            load_B(sm, t + 1, (t + 1) & 1, quarter, tid);
            cpwait<1>();
        } else {
            cpwait<0>();
        }
        __syncthreads();

        const char* Bb = sm.B[t & 1];

        #pragma unroll
        for (int grp = 0; grp < 2; grp++) {               // 2 groups of 4 n-blocks
            float c[2][4][4];
            #pragma unroll
            for (int mt = 0; mt < 2; mt++)
                #pragma unroll
                for (int u = 0; u < 4; u++)
                    c[mt][u][0] = c[mt][u][1] = c[mt][u][2] = c[mt][u][3] = 0.f;

            #pragma unroll
            for (int ks = 0; ks < 8; ks++) {
                int kb = ks * 32 + q * 4;
                uint32_t b0[4], b1[4];
                #pragma unroll
                for (int u = 0; u < 4; u++) {
                    const char* bp = &Bb[((grp * 4 + u) * 8 + g) * LDB + kb];
                    b0[u] = *reinterpret_cast<const uint32_t*>(bp);
                    b1[u] = *reinterpret_cast<const uint32_t*>(bp + 16);
                }
                // each B fragment feeds both A tiles
                #pragma unroll
                for (int u = 0; u < 4; u++) {
                    mma_fp8(c[0][u], a[0][ks], b0[u], b1[u]);
                    mma_fp8(c[1][u], a[1][ks], b0[u], b1[u]);
                }
            }

            // fused epilogue: dist = acc + cntR[col]; min
            #pragma unroll
            for (int u = 0; u < 4; u++) {
                int colbase = t * 64 + (grp * 4 + u) * 8 + q * 2;
                float2 cr = *reinterpret_cast<const float2*>(&sm.cntR[colbase]);
                #pragma unroll
                for (int mt = 0; mt < 2; mt++) {
                    rmin[mt][0] = fminf(rmin[mt][0],
                                        fminf(c[mt][u][0] + cr.x, c[mt][u][1] + cr.y));
                    rmin[mt][1] = fminf(rmin[mt][1],
                                        fminf(c[mt][u][2] + cr.x, c[mt][u][3] + cr.y));
                }
            }
        }
        __syncthreads();
    }

    // combine quads; then quarters via int atomicMin on float bits (all >= 0)
    #pragma unroll
    for (int mt = 0; mt < 2; mt++) {
        #pragma unroll
        for (int h = 0; h < 2; h++) {
            float v = rmin[mt][h];
            v = fminf(v, __shfl_xor_sync(0xffffffffu, v, 1));
            v = fminf(v, __shfl_xor_sync(0xffffffffu, v, 2));
            if (q == 0)
                atomicMin(&outi[mtile * MT + wid * 32 + mt * 16 + h * 8 + g],
                          __float_as_int(v));
        }
    }
}

// ---------------------------------------------------------------------------
extern "C" void kernel_launch(void* const* d_in, const int* in_sizes, int n_in,
                              void* d_out, int out_size) {
    const float* states = (const float*)d_in[0];
    const float* R      = (const float*)d_in[1];
    int* outi           = (int*)d_out;

    const int prepThreads = NREF * KDIM / 4 + NREF * 32;   // 196608
    prep_kernel<<<(prepThreads + 255) / 256, 256>>>(R, outi);

    cudaFuncSetAttribute(hamming_qmma, cudaFuncAttributeMaxDynamicSharedMemorySize, SMEM_SZ);
    hamming_qmma<<<(BATCH / MT) * 4, 128, SMEM_SZ>>>(states, outi);
}

// round 8
// speedup vs baseline: 1.1721x; 1.1721x over previous
#include <cuda_runtime.h>
#include <cuda_fp16.h>
#include <cstdint>

#define BATCH 8192
#define NREF  2048
#define KDIM  256
#define MT    128             // M rows per CTA (4 warps x 32 rows)
#define NQ    512             // refs per CTA (grid = 64 mtiles x 4 quarters)
#define NT    64              // refs per tile
#define NTILES (NQ / NT)      // 8
#define ROWB  512             // bytes per f16 row (256 halves)
#define LDB   528             // padded smem row stride (bytes)

__device__ __half g_Rh[NREF * KDIM];    // (1 - 2R) = +-1 in f16
__device__ float  g_cntR[NREF];

struct Smem {
    char   B[2][NT * LDB];    // 2 x 33792 B
    __half cntR[NQ];          // 1024 B
};
#define SMEM_SZ (int)sizeof(Smem)

// ---------------------------------------------------------------------------
__device__ __forceinline__ uint32_t s2u(const void* p) {
    uint32_t a;
    asm("{ .reg .u64 t; cvta.to.shared.u64 t, %1; cvt.u32.u64 %0, t; }" : "=r"(a) : "l"(p));
    return a;
}
__device__ __forceinline__ void cpa16(uint32_t dst, const void* src) {
    asm volatile("cp.async.cg.shared.global [%0], [%1], 16;" :: "r"(dst), "l"(src));
}
template <int N>
__device__ __forceinline__ void cpwait() {
    asm volatile("cp.async.wait_group %0;" :: "n"(N) : "memory");
}
// f16 MMA with F16 ACCUMULATORS (half the accumulator bandwidth of f32)
__device__ __forceinline__ void mma_f16(uint32_t* c, const uint32_t* a,
                                        uint32_t b0, uint32_t b1) {
    asm volatile(
        "mma.sync.aligned.m16n8k16.row.col.f16.f16.f16.f16 "
        "{%0,%1},{%2,%3,%4,%5},{%6,%7},{%0,%1};"
        : "+r"(c[0]), "+r"(c[1])
        : "r"(a[0]), "r"(a[1]), "r"(a[2]), "r"(a[3]), "r"(b0), "r"(b1));
}
__device__ __forceinline__ uint32_t packh2(float x, float y) {
    __half2 h = __floats2half2_rn(x, y);
    return *reinterpret_cast<uint32_t*>(&h);
}

// ---------------------------------------------------------------------------
// Kernel 1 (prep): out init, R fp32 -> f16 of (1-2R), cntR reduce. Exact.
// ---------------------------------------------------------------------------
__global__ void prep_kernel(const float* __restrict__ R, int* __restrict__ outi) {
    const int Rn4 = NREF * KDIM / 4;    // 131072
    int i = blockIdx.x * 256 + threadIdx.x;

    if (i < BATCH) outi[i] = 0x7f800000;   // +inf bits

    if (i < Rn4) {
        float4 v = reinterpret_cast<const float4*>(R)[i];
        // R==0 -> +1 (0x3C00), R==1 -> -1 (0xBC00)
        uint32_t h0 = 0x3C00u | ((uint32_t)v.x << 15);
        uint32_t h1 = 0x3C00u | ((uint32_t)v.y << 15);
        uint32_t h2 = 0x3C00u | ((uint32_t)v.z << 15);
        uint32_t h3 = 0x3C00u | ((uint32_t)v.w << 15);
        uint2 o;
        o.x = h0 | (h1 << 16);
        o.y = h2 | (h3 << 16);
        reinterpret_cast<uint2*>(g_Rh)[i] = o;
    } else if (i < Rn4 + NREF * 32) {
        int t = i - Rn4;
        int w = t >> 5, lane = t & 31;
        float s = 0.f;
        #pragma unroll
        for (int k = lane; k < KDIM; k += 32) s += R[w * KDIM + k];
        #pragma unroll
        for (int o = 16; o; o >>= 1) s += __shfl_xor_sync(0xffffffffu, s, o);
        if (lane == 0) g_cntR[w] = s;
    }
}

// ---------------------------------------------------------------------------
// Kernel 2 (main): f16 HMMA with f16 accumulation (exact: all values are
// integers bounded by 512 << 2048). Warp owns 32 M-rows; B double-buffered
// cp.async; packed half2 min epilogue; float-bit atomicMin combine.
// ---------------------------------------------------------------------------
__device__ __forceinline__ void load_B(Smem& sm, int t, int buf, int quarter, int tid) {
    const char* src = (const char*)g_Rh + ((size_t)(quarter * NQ + t * NT)) * ROWB;
    #pragma unroll
    for (int j = 0; j < 16; j++) {           // 2048 x 16B chunks / 128 threads
        int i = tid + j * 128;
        int r = i >> 5, c = i & 31;          // 32 chunks per 512B row
        cpa16(s2u(&sm.B[buf][r * LDB + c * 16]), src + (size_t)r * ROWB + c * 16);
    }
    asm volatile("cp.async.commit_group;" ::: "memory");
}

__global__ void __launch_bounds__(128, 2) hamming_h16(const float* __restrict__ S,
                                                      int* __restrict__ outi) {
    extern __shared__ __align__(16) char smraw[];
    Smem& sm = *reinterpret_cast<Smem*>(smraw);

    const int tid  = threadIdx.x;
    const int wid  = tid >> 5;
    const int lane = tid & 31;
    const int g    = lane >> 2;
    const int q    = lane & 3;
    const int mtile   = blockIdx.x >> 2;
    const int quarter = blockIdx.x & 3;

    load_B(sm, 0, 0, quarter, tid);                       // tile 0 in flight

    // A fragments from float S: 2 m16-tiles x 16 k-steps x 4 regs (f16 0/1)
    uint32_t a[2][16][4];
    #pragma unroll
    for (int mt = 0; mt < 2; mt++) {
        const float* rowLo = S + ((size_t)(mtile * MT + wid * 32 + mt * 16 + g)) * KDIM;
        const float* rowHi = rowLo + 8 * KDIM;
        #pragma unroll
        for (int ks = 0; ks < 16; ks++) {
            int k0 = ks * 16 + q * 2;
            float2 lo0 = *reinterpret_cast<const float2*>(rowLo + k0);
            float2 hi0 = *reinterpret_cast<const float2*>(rowHi + k0);
            float2 lo1 = *reinterpret_cast<const float2*>(rowLo + k0 + 8);
            float2 hi1 = *reinterpret_cast<const float2*>(rowHi + k0 + 8);
            a[mt][ks][0] = packh2(lo0.x, lo0.y);
            a[mt][ks][1] = packh2(hi0.x, hi0.y);
            a[mt][ks][2] = packh2(lo1.x, lo1.y);
            a[mt][ks][3] = packh2(hi1.x, hi1.y);
        }
    }
    for (int i = tid; i < NQ; i += 128)
        sm.cntR[i] = __float2half_rn(g_cntR[quarter * NQ + i]);

    // running min as packed half2 (both halves +inf)
    uint32_t rmin2[2][2] = {{0x7C007C00u, 0x7C007C00u}, {0x7C007C00u, 0x7C007C00u}};

    for (int t = 0; t < NTILES; t++) {
        if (t + 1 < NTILES) {
            load_B(sm, t + 1, (t + 1) & 1, quarter, tid);
            cpwait<1>();
        } else {
            cpwait<0>();
        }
        __syncthreads();

        const char* Bb = sm.B[t & 1];

        #pragma unroll
        for (int grp = 0; grp < 2; grp++) {               // 2 groups of 4 n-blocks
            uint32_t c[2][4][2];
            #pragma unroll
            for (int mt = 0; mt < 2; mt++)
                #pragma unroll
                for (int u = 0; u < 4; u++)
                    c[mt][u][0] = c[mt][u][1] = 0u;

            #pragma unroll
            for (int ks = 0; ks < 16; ks++) {
                int kb = ks * 32 + q * 4;
                uint32_t b0[4], b1[4];
                #pragma unroll
                for (int u = 0; u < 4; u++) {
                    const char* bp = &Bb[((grp * 4 + u) * 8 + g) * LDB + kb];
                    b0[u] = *reinterpret_cast<const uint32_t*>(bp);
                    b1[u] = *reinterpret_cast<const uint32_t*>(bp + 16);
                }
                #pragma unroll
                for (int u = 0; u < 4; u++) {
                    mma_f16(c[0][u], a[0][ks], b0[u], b1[u]);
                    mma_f16(c[1][u], a[1][ks], b0[u], b1[u]);
                }
            }

            // packed epilogue: dist = acc + cntR(pair); hmin2
            #pragma unroll
            for (int u = 0; u < 4; u++) {
                int colbase = t * 64 + (grp * 4 + u) * 8 + q * 2;
                uint32_t cr = *reinterpret_cast<const uint32_t*>(&sm.cntR[colbase]);
                __half2 crh = *reinterpret_cast<__half2*>(&cr);
                #pragma unroll
                for (int mt = 0; mt < 2; mt++) {
                    __half2 d0 = __hadd2(*reinterpret_cast<__half2*>(&c[mt][u][0]), crh);
                    __half2 d1 = __hadd2(*reinterpret_cast<__half2*>(&c[mt][u][1]), crh);
                    __half2 m0 = __hmin2(*reinterpret_cast<__half2*>(&rmin2[mt][0]), d0);
                    __half2 m1 = __hmin2(*reinterpret_cast<__half2*>(&rmin2[mt][1]), d1);
                    rmin2[mt][0] = *reinterpret_cast<uint32_t*>(&m0);
                    rmin2[mt][1] = *reinterpret_cast<uint32_t*>(&m1);
                }
            }
        }
        __syncthreads();
    }

    // reduce half2 -> float, combine quads, then quarters via atomicMin
    #pragma unroll
    for (int mt = 0; mt < 2; mt++) {
        #pragma unroll
        for (int h = 0; h < 2; h++) {
            __half2 p = *reinterpret_cast<__half2*>(&rmin2[mt][h]);
            float v = fminf(__low2float(p), __high2float(p));
            v = fminf(v, __shfl_xor_sync(0xffffffffu, v, 1));
            v = fminf(v, __shfl_xor_sync(0xffffffffu, v, 2));
            if (q == 0)
                atomicMin(&outi[mtile * MT + wid * 32 + mt * 16 + h * 8 + g],
                          __float_as_int(v));
        }
    }
}

// ---------------------------------------------------------------------------
extern "C" void kernel_launch(void* const* d_in, const int* in_sizes, int n_in,
                              void* d_out, int out_size) {
    const float* states = (const float*)d_in[0];
    const float* R      = (const float*)d_in[1];
    int* outi           = (int*)d_out;

    const int prepThreads = NREF * KDIM / 4 + NREF * 32;   // 196608
    prep_kernel<<<(prepThreads + 255) / 256, 256>>>(R, outi);

    cudaFuncSetAttribute(hamming_h16, cudaFuncAttributeMaxDynamicSharedMemorySize, SMEM_SZ);
    hamming_h16<<<(BATCH / MT) * 4, 128, SMEM_SZ>>>(states, outi);
}

// round 9
// speedup vs baseline: 1.5548x; 1.3265x over previous
#include <cuda_runtime.h>
#include <cuda_fp16.h>
#include <cstdint>

#define BATCH 8192
#define NREF  2048
#define KDIM  256
#define MT    128             // M rows per CTA (4 warps x 32 rows)
#define NPACK 1024            // packed columns total (2 refs each)
#define NQ    256             // packed cols per CTA quarter
#define NT    64              // packed cols per tile
#define NTILES (NQ / NT)      // 4
#define ROWB  512             // bytes per packed-col row (256 halves)
#define LDB   528             // padded smem row stride (bytes)

// g_Bp[j][k]: f16 (1-2R[2j][k]) + 1024*(1-2R[2j+1][k]), j = packed col
__device__ __half g_Bp[NPACK * KDIM];
__device__ float  g_cntR[NREF];

struct Smem {
    char  B[2][NT * LDB];     // 2 x 33792 B
    float cntR[2 * NQ];       // 512 refs of this quarter (2048 B)
};
#define SMEM_SZ (int)sizeof(Smem)

// ---------------------------------------------------------------------------
__device__ __forceinline__ uint32_t s2u(const void* p) {
    uint32_t a;
    asm("{ .reg .u64 t; cvta.to.shared.u64 t, %1; cvt.u32.u64 %0, t; }" : "=r"(a) : "l"(p));
    return a;
}
__device__ __forceinline__ void cpa16(uint32_t dst, const void* src) {
    asm volatile("cp.async.cg.shared.global [%0], [%1], 16;" :: "r"(dst), "l"(src));
}
template <int N>
__device__ __forceinline__ void cpwait() {
    asm volatile("cp.async.wait_group %0;" :: "n"(N) : "memory");
}
// f16 inputs, f32 accumulators (exact for integers < 2^24)
__device__ __forceinline__ void mma_f16f32(float* c, const uint32_t* a,
                                           uint32_t b0, uint32_t b1) {
    asm volatile(
        "mma.sync.aligned.m16n8k16.row.col.f32.f16.f16.f32 "
        "{%0,%1,%2,%3},{%4,%5,%6,%7},{%8,%9},{%0,%1,%2,%3};"
        : "+f"(c[0]), "+f"(c[1]), "+f"(c[2]), "+f"(c[3])
        : "r"(a[0]), "r"(a[1]), "r"(a[2]), "r"(a[3]), "r"(b0), "r"(b1));
}
__device__ __forceinline__ uint32_t packh2(float x, float y) {
    __half2 h = __floats2half2_rn(x, y);
    return *reinterpret_cast<uint32_t*>(&h);
}

// ---------------------------------------------------------------------------
// Kernel 1 (prep): out init; pack ref pairs into f16 radix-1024 B; cntR.
// All values exact: B in {+-1023, +-1025} (f16-exact integers).
// ---------------------------------------------------------------------------
__global__ void prep_kernel(const float* __restrict__ R, int* __restrict__ outi) {
    int i = blockIdx.x * 256 + threadIdx.x;

    if (i < BATCH) outi[i] = 0x7f800000;   // +inf bits

    if (i < NPACK * 64) {                  // 65536: pack 4 k-values per thread
        int j = i >> 6, c = i & 63;        // packed col j, k-chunk c
        float4 r0 = *reinterpret_cast<const float4*>(R + (size_t)(2 * j) * KDIM + c * 4);
        float4 r1 = *reinterpret_cast<const float4*>(R + (size_t)(2 * j + 1) * KDIM + c * 4);
        uint32_t lo = packh2(1025.f - 2.f * r0.x - 2048.f * r1.x,
                             1025.f - 2.f * r0.y - 2048.f * r1.y);
        uint32_t hi = packh2(1025.f - 2.f * r0.z - 2048.f * r1.z,
                             1025.f - 2.f * r0.w - 2048.f * r1.w);
        uint2 o; o.x = lo; o.y = hi;
        reinterpret_cast<uint2*>(g_Bp)[(j * 64 + c)] = o;   // 4 halves = 8 B
    } else if (i < NPACK * 64 + NREF * 32) {
        int t = i - NPACK * 64;
        int w = t >> 5, lane = t & 31;
        float s = 0.f;
        #pragma unroll
        for (int k = lane; k < KDIM; k += 32) s += R[w * KDIM + k];
        #pragma unroll
        for (int o = 16; o; o >>= 1) s += __shfl_xor_sync(0xffffffffu, s, o);
        if (lane == 0) g_cntR[w] = s;
    }
}

// ---------------------------------------------------------------------------
// Kernel 2 (main): HMMA f16xf16->f32 on radix-1024 packed B: each MMA column
// carries TWO refs -> half the MMA instructions of the unpacked GEMM.
// Epilogue decodes (d0, d1) exactly and takes the running min.
// ---------------------------------------------------------------------------
__device__ __forceinline__ void load_B(Smem& sm, int t, int buf, int quarter, int tid) {
    const char* src = (const char*)g_Bp + ((size_t)(quarter * NQ + t * NT)) * ROWB;
    #pragma unroll
    for (int j = 0; j < 16; j++) {           // 2048 x 16B chunks / 128 threads
        int i = tid + j * 128;
        int r = i >> 5, c = i & 31;          // 32 chunks per 512B row
        cpa16(s2u(&sm.B[buf][r * LDB + c * 16]), src + (size_t)r * ROWB + c * 16);
    }
    asm volatile("cp.async.commit_group;" ::: "memory");
}

__device__ __forceinline__ void decode_min(float acc, float2 cr, float& rmin) {
    float d1 = rintf(acc * (1.0f / 1024.0f));      // |d0|/1024 <= 0.25 -> no ties
    float d0 = fmaf(d1, -1024.0f, acc);            // exact
    rmin = fminf(rmin, fminf(d0 + cr.x, d1 + cr.y));
}

__global__ void __launch_bounds__(128, 2) hamming_pk(const float* __restrict__ S,
                                                     int* __restrict__ outi) {
    extern __shared__ __align__(16) char smraw[];
    Smem& sm = *reinterpret_cast<Smem*>(smraw);

    const int tid  = threadIdx.x;
    const int wid  = tid >> 5;
    const int lane = tid & 31;
    const int g    = lane >> 2;
    const int q    = lane & 3;
    const int mtile   = blockIdx.x >> 2;
    const int quarter = blockIdx.x & 3;

    load_B(sm, 0, 0, quarter, tid);                       // tile 0 in flight

    // A fragments from float S: 2 m16-tiles x 16 k-steps x 4 regs (f16 0/1)
    uint32_t a[2][16][4];
    #pragma unroll
    for (int mt = 0; mt < 2; mt++) {
        const float* rowLo = S + ((size_t)(mtile * MT + wid * 32 + mt * 16 + g)) * KDIM;
        const float* rowHi = rowLo + 8 * KDIM;
        #pragma unroll
        for (int ks = 0; ks < 16; ks++) {
            int k0 = ks * 16 + q * 2;
            float2 lo0 = *reinterpret_cast<const float2*>(rowLo + k0);
            float2 hi0 = *reinterpret_cast<const float2*>(rowHi + k0);
            float2 lo1 = *reinterpret_cast<const float2*>(rowLo + k0 + 8);
            float2 hi1 = *reinterpret_cast<const float2*>(rowHi + k0 + 8);
            a[mt][ks][0] = packh2(lo0.x, lo0.y);
            a[mt][ks][1] = packh2(hi0.x, hi0.y);
            a[mt][ks][2] = packh2(lo1.x, lo1.y);
            a[mt][ks][3] = packh2(hi1.x, hi1.y);
        }
    }
    // this quarter's 512 cntR values (pairs indexed by packed col)
    for (int i = tid; i < 2 * NQ; i += 128) sm.cntR[i] = g_cntR[quarter * 2 * NQ + i];

    float rmin[2][2] = {{__int_as_float(0x7f800000), __int_as_float(0x7f800000)},
                        {__int_as_float(0x7f800000), __int_as_float(0x7f800000)}};

    for (int t = 0; t < NTILES; t++) {
        if (t + 1 < NTILES) {
            load_B(sm, t + 1, (t + 1) & 1, quarter, tid);
            cpwait<1>();
        } else {
            cpwait<0>();
        }
        __syncthreads();

        const char* Bb = sm.B[t & 1];
        const float2* cr2 = reinterpret_cast<const float2*>(sm.cntR);

        #pragma unroll
        for (int grp = 0; grp < 2; grp++) {               // 2 groups of 4 n-blocks
            float c[2][4][4];
            #pragma unroll
            for (int mt = 0; mt < 2; mt++)
                #pragma unroll
                for (int u = 0; u < 4; u++)
                    c[mt][u][0] = c[mt][u][1] = c[mt][u][2] = c[mt][u][3] = 0.f;

            #pragma unroll
            for (int ks = 0; ks < 16; ks++) {
                int kb = ks * 32 + q * 4;
                uint32_t b0[4], b1[4];
                #pragma unroll
                for (int u = 0; u < 4; u++) {
                    const char* bp = &Bb[((grp * 4 + u) * 8 + g) * LDB + kb];
                    b0[u] = *reinterpret_cast<const uint32_t*>(bp);
                    b1[u] = *reinterpret_cast<const uint32_t*>(bp + 16);
                }
                #pragma unroll
                for (int u = 0; u < 4; u++) {
                    mma_f16f32(c[0][u], a[0][ks], b0[u], b1[u]);
                    mma_f16f32(c[1][u], a[1][ks], b0[u], b1[u]);
                }
            }

            // decode epilogue: each acc column carries 2 refs
            #pragma unroll
            for (int u = 0; u < 4; u++) {
                int colbase = t * 64 + (grp * 4 + u) * 8 + q * 2;   // packed col
                float2 cra = cr2[colbase];       // refs 2*colbase, 2*colbase+1
                float2 crb = cr2[colbase + 1];
                #pragma unroll
                for (int mt = 0; mt < 2; mt++) {
                    decode_min(c[mt][u][0], cra, rmin[mt][0]);
                    decode_min(c[mt][u][1], crb, rmin[mt][0]);
                    decode_min(c[mt][u][2], cra, rmin[mt][1]);
                    decode_min(c[mt][u][3], crb, rmin[mt][1]);
                }
            }
        }
        __syncthreads();
    }

    // combine quads; quarters via int atomicMin on float bits (all >= 0)
    #pragma unroll
    for (int mt = 0; mt < 2; mt++) {
        #pragma unroll
        for (int h = 0; h < 2; h++) {
            float v = rmin[mt][h];
            v = fminf(v, __shfl_xor_sync(0xffffffffu, v, 1));
            v = fminf(v, __shfl_xor_sync(0xffffffffu, v, 2));
            if (q == 0)
                atomicMin(&outi[mtile * MT + wid * 32 + mt * 16 + h * 8 + g],
                          __float_as_int(v));
        }
    }
}

// ---------------------------------------------------------------------------
extern "C" void kernel_launch(void* const* d_in, const int* in_sizes, int n_in,
                              void* d_out, int out_size) {
    const float* states = (const float*)d_in[0];
    const float* R      = (const float*)d_in[1];
    int* outi           = (int*)d_out;

    const int prepThreads = NPACK * 64 + NREF * 32;   // 131072
    prep_kernel<<<(prepThreads + 255) / 256, 256>>>(R, outi);

    cudaFuncSetAttribute(hamming_pk, cudaFuncAttributeMaxDynamicSharedMemorySize, SMEM_SZ);
    hamming_pk<<<(BATCH / MT) * 4, 128, SMEM_SZ>>>(states, outi);
}